// round 1
// baseline (speedup 1.0000x reference)
#include <cuda_runtime.h>

#define T_DIM 1024
#define F_DIM 256
#define UNITS 32
#define AW    64
#define B_DIM 4
#define NROWS (B_DIM * T_DIM)

// Scratch for projected q (with bh folded in) and k. 2 x 512KB.
__device__ float g_q[NROWS * UNITS];
__device__ float g_k[NROWS * UNITS];

__device__ __forceinline__ float tanh_approx(float x) {
    float y;
    asm("tanh.approx.f32 %0, %1;" : "=f"(y) : "f"(x));
    return y;
}

// ---------------------------------------------------------------------------
// Kernel 1: q[row,u] = x[row]·Wt[:,u] + bh[u];  k[row,u] = x[row]·Wx[:,u]
// 256 blocks x 256 threads, 16 rows per block. x rows staged in smem so each
// warp streams its W matrix once (L1-resident) and applies it to 4 rows.
// ---------------------------------------------------------------------------
__global__ void __launch_bounds__(256) qk_kernel(
    const float* __restrict__ x,
    const float* __restrict__ Wt,
    const float* __restrict__ Wx,
    const float* __restrict__ bh)
{
    __shared__ float xs[16 * F_DIM];   // 16KB

    const int tid = threadIdx.x;
    const int r0  = blockIdx.x * 16;

    // Stage 16 contiguous rows (16KB) via float4, fully coalesced.
    const float4* xg  = reinterpret_cast<const float4*>(x) + (size_t)r0 * (F_DIM / 4);
    float4*       xs4 = reinterpret_cast<float4*>(xs);
    #pragma unroll
    for (int i = 0; i < 4; i++)
        xs4[tid + i * 256] = xg[tid + i * 256];
    __syncthreads();

    const int  wid  = tid >> 5;
    const int  lane = tid & 31;
    const bool is_q = (wid < 4);
    const float* __restrict__ W = is_q ? Wt : Wx;
    const int  rb   = (wid & 3) * 4;   // 4 rows per warp

    float acc[4] = {0.f, 0.f, 0.f, 0.f};
    const float* xr0 = xs + (rb + 0) * F_DIM;
    const float* xr1 = xs + (rb + 1) * F_DIM;
    const float* xr2 = xs + (rb + 2) * F_DIM;
    const float* xr3 = xs + (rb + 3) * F_DIM;

    #pragma unroll 8
    for (int f = 0; f < F_DIM; f++) {
        const float wv = W[f * UNITS + lane];   // 128B coalesced per warp
        acc[0] += xr0[f] * wv;   // smem broadcast reads
        acc[1] += xr1[f] * wv;
        acc[2] += xr2[f] * wv;
        acc[3] += xr3[f] * wv;
    }

    const float bias = is_q ? bh[lane] : 0.f;   // fold bh into q
    float* __restrict__ G = is_q ? g_q : g_k;
    #pragma unroll
    for (int r = 0; r < 4; r++)
        G[(size_t)(r0 + rb + r) * UNITS + lane] = acc[r] + bias;
}

// ---------------------------------------------------------------------------
// Kernel 2: per (b,t) block — band logits + softmax + weighted sum of x rows.
// grid (T, B), 256 threads (8 warps).
// ---------------------------------------------------------------------------
__global__ void __launch_bounds__(256) attn_kernel(
    const float* __restrict__ x,
    const float* __restrict__ Wa,
    const float* __restrict__ ba,
    float* __restrict__ out)
{
    const int t   = blockIdx.x;
    const int b   = blockIdx.y;
    const int row = b * T_DIM + t;

    __shared__ float  qs[UNITS];
    __shared__ float  was[UNITS];
    __shared__ float  es[AW];
    __shared__ float4 part[256];

    const int tid  = threadIdx.x;
    const int wid  = tid >> 5;
    const int lane = tid & 31;

    if (tid < UNITS) {
        qs[tid]  = g_q[(size_t)row * UNITS + tid];   // bh already folded in
        was[tid] = Wa[tid];
    }
    __syncthreads();

    const int s0 = max(0, t - AW / 2);
    const int s1 = min(T_DIM, t - AW / 2 + AW);
    const int n  = s1 - s0;
    const float bav = ba[0];

    // --- Phase B: e[j] = Wa · tanh(q + k_s) + ba over the band -------------
    {
        const float q  = qs[lane];
        const float wa = was[lane];
        for (int j = wid; j < n; j += 8) {
            const int s = s0 + j;
            float v = wa * tanh_approx(q + g_k[(size_t)(b * T_DIM + s) * UNITS + lane]);
            #pragma unroll
            for (int o = 16; o; o >>= 1)
                v += __shfl_xor_sync(0xffffffffu, v, o);
            if (lane == 0) es[j] = v + bav;
        }
    }
    __syncthreads();

    // --- Phase C: softmax over band (warp 0). Masked entries underflow to 0
    //     in the reference (exp(-10000) == 0 in fp32), so band-only is exact.
    if (wid == 0) {
        const float e0 = (lane      < n) ? es[lane]      : -1e30f;
        const float e1 = (lane + 32 < n) ? es[lane + 32] : -1e30f;
        float m = fmaxf(e0, e1);
        #pragma unroll
        for (int o = 16; o; o >>= 1)
            m = fmaxf(m, __shfl_xor_sync(0xffffffffu, m, o));
        const float p0 = (lane      < n) ? __expf(e0 - m) : 0.f;
        const float p1 = (lane + 32 < n) ? __expf(e1 - m) : 0.f;
        float s = p0 + p1;
        #pragma unroll
        for (int o = 16; o; o >>= 1)
            s += __shfl_xor_sync(0xffffffffu, s, o);
        const float inv = 1.f / s;
        es[lane]      = p0 * inv;
        es[lane + 32] = p1 * inv;
    }
    __syncthreads();

    // --- Phase D: v[f] = sum_j a[j] * x[s0+j, f], float4 vectorized --------
    const int quad = tid >> 6;   // 0..3 j-partition
    const int f4   = tid & 63;   // 64 float4 = 256 floats
    const float4* __restrict__ x4 =
        reinterpret_cast<const float4*>(x) + (size_t)(b * T_DIM) * (F_DIM / 4);

    float4 acc = make_float4(0.f, 0.f, 0.f, 0.f);
    for (int j = quad; j < n; j += 4) {
        const float  a  = es[j];
        const float4 xv = x4[(size_t)(s0 + j) * (F_DIM / 4) + f4];
        acc.x += a * xv.x;
        acc.y += a * xv.y;
        acc.z += a * xv.z;
        acc.w += a * xv.w;
    }
    part[tid] = acc;
    __syncthreads();

    if (tid < 64) {
        float4 a0 = part[tid];
        const float4 a1 = part[tid + 64];
        const float4 a2 = part[tid + 128];
        const float4 a3 = part[tid + 192];
        a0.x += a1.x + a2.x + a3.x;
        a0.y += a1.y + a2.y + a3.y;
        a0.z += a1.z + a2.z + a3.z;
        a0.w += a1.w + a2.w + a3.w;
        reinterpret_cast<float4*>(out)[(size_t)row * (F_DIM / 4) + tid] = a0;
    }
}

extern "C" void kernel_launch(void* const* d_in, const int* in_sizes, int n_in,
                              void* d_out, int out_size)
{
    const float* x  = (const float*)d_in[0];
    const float* Wt = (const float*)d_in[1];
    const float* Wx = (const float*)d_in[2];
    const float* bh = (const float*)d_in[3];
    const float* Wa = (const float*)d_in[4];
    const float* ba = (const float*)d_in[5];
    float* out = (float*)d_out;

    qk_kernel<<<NROWS / 16, 256>>>(x, Wt, Wx, bh);
    attn_kernel<<<dim3(T_DIM, B_DIM), 256>>>(x, Wa, ba, out);
}